// round 11
// baseline (speedup 1.0000x reference)
#include <cuda_runtime.h>

// SoftDTW forward, B=128, N=M=512, gamma=1.
// S = exp(-R):  S[i][j] = exp(-D[i][j]) * (S[i-1][j-1] + S[i-1][j] + S[i][j-1])
// Final: R = -(ln S + Es*ln2), warp-uniform power-of-2 rescaling every 5 phases.
//
// One CTA per batch, 4 warps, TWO ROWS PER STEP (287 steps):
//   lane l at step s computes rows 2(s-l), 2(s-l)+1 of cols [16l,16l+16).
//   Neighbor data: lane l-1's boundary at 3 half-step times via 3 shfl_up.
//   warps 0-2: producers — ping-pong reg buffers (load block t+2 before storing
//              block t+1), exp(-D) into a 44-slot smem ring; slot (rp+l)%44.
//   warp 3:    consumer — steady-region elementwise p-terms computed with packed
//              f32x2 add/mul (halves fma-pipe instruction count; serial chain
//              stays scalar FFMA). Guarded head/tail keeps the scalar path.

namespace {
constexpr int BATCH   = 128;
constexpr int NR      = 512;
constexpr int MC      = 512;
constexpr int NRP     = 256;                     // row pairs
constexpr int KP      = 6;                       // steps (row-pairs) per phase
constexpr int RS      = 44;                      // ring slots
constexpr int LSTRIDE = 36;                      // words per lane chunk (32 used + pad)
constexpr int SLOTW   = 32 * LSTRIDE;            // 1152 words per slot
constexpr int SMEM_BYTES = RS * SLOTW * 4;       // 202752
constexpr int STEPS   = NRP + 31;                // 287
constexpr int NPHASE  = (STEPS + KP - 1) / KP;   // 48 (even)
constexpr unsigned FULL = 0xffffffffu;
}

typedef unsigned long long u64;

__device__ __forceinline__ u64 padd(u64 a, u64 b) {
    u64 r; asm("add.rn.f32x2 %0, %1, %2;" : "=l"(r) : "l"(a), "l"(b)); return r;
}
__device__ __forceinline__ u64 pmul(u64 a, u64 b) {
    u64 r; asm("mul.rn.f32x2 %0, %1, %2;" : "=l"(r) : "l"(a), "l"(b)); return r;
}
__device__ __forceinline__ u64 pk(float lo, float hi) {
    u64 r; asm("mov.b64 %0, {%1, %2};" : "=l"(r) : "f"(lo), "f"(hi)); return r;
}
__device__ __forceinline__ float2 up(u64 v) {
    float2 r; asm("mov.b64 {%0, %1}, %2;" : "=f"(r.x), "=f"(r.y) : "l"(v)); return r;
}

__device__ __forceinline__ float4 exp4neg(float4 v) {
    float4 r;
    r.x = __expf(-v.x); r.y = __expf(-v.y);
    r.z = __expf(-v.z); r.w = __expf(-v.w);
    return r;
}

__global__ __launch_bounds__(128, 1)
void softdtw_fwd(const float* __restrict__ D, float* __restrict__ out) {
    extern __shared__ float sm[];
    const int b   = blockIdx.x;
    const int tid = threadIdx.x;
    const int w   = tid >> 5;
    const int l   = tid & 31;
    const float* __restrict__ G = D + (size_t)b * NR * MC + l * 16;

    if (w < 3) {
        // ---------------- producers (warps 0,1,2) ----------------
        float* lane_base = sm + l * LSTRIDE;

        auto load4 = [&](int r0, float4 a[16]) {         // rows r0..r0+3
            #pragma unroll
            for (int rr = 0; rr < 4; ++rr) {
                const float4* s = (const float4*)(G + (size_t)(r0 + rr) * MC);
                a[rr * 4 + 0] = s[0]; a[rr * 4 + 1] = s[1];
                a[rr * 4 + 2] = s[2]; a[rr * 4 + 3] = s[3];
            }
        };
        auto store_pair = [&](int rp, const float4 a[8]) {  // rows 2rp, 2rp+1
            float4* dst = (float4*)(lane_base + ((rp + l) % RS) * SLOTW);
            #pragma unroll
            for (int c = 0; c < 8; ++c) dst[c] = exp4neg(a[c]);
        };
        auto store_block = [&](int rp0, const float4 a[16]) {
            store_pair(rp0,     a);
            store_pair(rp0 + 1, a + 8);
        };

        // phase-block k supplies row-pairs [6k, 6k+6); this warp owns rp0 = 6k+2w.
        {   // block 0 before the first barrier
            float4 T[16];
            load4(4 * w, T);
            store_block(2 * w, T);
        }
        float4 X[16], Y[16];
        load4(12 + 4 * w, X);                            // block 1

        for (int t = 0; t + 1 < NPHASE; t += 2) {
            __syncthreads();
            {   // phase t: load block t+2 first (full-phase lead), store block t+1
                const int rf = 12 * (t + 2) + 4 * w;
                if (rf < NR) load4(rf, Y);
                const int rp0 = 6 * (t + 1) + 2 * w;
                if (rp0 + 1 < NRP) store_block(rp0, X);
            }
            __syncthreads();
            {   // phase t+1
                const int rf = 12 * (t + 3) + 4 * w;
                if (rf < NR) load4(rf, X);
                const int rp0 = 6 * (t + 2) + 2 * w;
                if (rp0 + 1 < NRP) store_block(rp0, Y);
            }
        }
    } else {
        // ---------------- consumer (warp 3) ----------------
        float h[16];
        #pragma unroll
        for (int j = 0; j < 16; ++j) h[j] = 0.f;
        float o15 = 0.f;   // h15 two half-steps back: S[2rp-1][16l+15] pre-step
        float m15 = 0.f;   // mid-step h15:            S[2rp  ][16l+15]
        int   Es = 0;
        int   slot = 0;
        const float* lane_base = sm + l * LSTRIDE;

        auto rescale = [&]() {
            float m = h[0];
            #pragma unroll
            for (int j = 1; j < 16; ++j) m = fmaxf(m, h[j]);
            #pragma unroll
            for (int o = 16; o; o >>= 1)
                m = fmaxf(m, __shfl_xor_sync(FULL, m, o));
            if (m > 0.f) {
                const int   k = (__float_as_int(m) >> 23) - 127;
                const float f = __int_as_float((127 - k) << 23);
                #pragma unroll
                for (int j = 0; j < 16; ++j) h[j] *= f;
                o15 *= f; m15 *= f;
                Es += k;
            }
        };

        for (int t = 0; t < NPHASE; ++t) {
            __syncthreads();
            if (t >= 6 && t <= 41) {
                // ---- steady: steps 36..251, every lane active; packed f32x2 ----
                #pragma unroll
                for (int q = 0; q < KP; ++q) {
                    const float4* eb = (const float4*)(lane_base + slot * SLOTW);
                    const float4 A0 = eb[0], A1 = eb[1], A2 = eb[2], A3 = eb[3];
                    const float4 B0 = eb[4], B1 = eb[5], B2 = eb[6], B3 = eb[7];
                    float z0 = __shfl_up_sync(FULL, o15, 1);   // diag row a
                    float z1 = __shfl_up_sync(FULL, m15, 1);   // left a / diag b
                    float z2 = __shfl_up_sync(FULL, h[15], 1); // left row b
                    if (l == 0) { z0 = 0.f; z1 = 0.f; z2 = 0.f; }

                    const float ea[16] = { A0.x, A0.y, A0.z, A0.w,
                                           A1.x, A1.y, A1.z, A1.w,
                                           A2.x, A2.y, A2.z, A2.w,
                                           A3.x, A3.y, A3.z, A3.w };
                    const float ebv[16] = { B0.x, B0.y, B0.z, B0.w,
                                            B1.x, B1.y, B1.z, B1.w,
                                            B2.x, B2.y, B2.z, B2.w,
                                            B3.x, B3.y, B3.z, B3.w };
                    const u64 EA[8] = { pk(A0.x,A0.y), pk(A0.z,A0.w),
                                        pk(A1.x,A1.y), pk(A1.z,A1.w),
                                        pk(A2.x,A2.y), pk(A2.z,A2.w),
                                        pk(A3.x,A3.y), pk(A3.z,A3.w) };
                    const u64 EB[8] = { pk(B0.x,B0.y), pk(B0.z,B0.w),
                                        pk(B1.x,B1.y), pk(B1.z,B1.w),
                                        pk(B2.x,B2.y), pk(B2.z,B2.w),
                                        pk(B3.x,B3.y), pk(B3.z,B3.w) };

                    // row a: packed p-terms  pa[2k,2k+1] = ea ⊙ (h[j-1]+h[j])
                    float2 pa[8];
                    pa[0] = up(pmul(EA[0], padd(pk(z0, h[0]), pk(h[0], h[1]))));
                    #pragma unroll
                    for (int k = 1; k < 8; ++k)
                        pa[k] = up(pmul(EA[k], padd(pk(h[2*k-1], h[2*k]),
                                                    pk(h[2*k],   h[2*k+1]))));
                    float av[16];
                    float c = z1;
                    #pragma unroll
                    for (int k = 0; k < 8; ++k) {
                        c = fmaf(ea[2*k],   c, pa[k].x); av[2*k]   = c;
                        c = fmaf(ea[2*k+1], c, pa[k].y); av[2*k+1] = c;
                    }
                    // row b
                    float2 pb[8];
                    pb[0] = up(pmul(EB[0], padd(pk(z1, av[0]), pk(av[0], av[1]))));
                    #pragma unroll
                    for (int k = 1; k < 8; ++k)
                        pb[k] = up(pmul(EB[k], padd(pk(av[2*k-1], av[2*k]),
                                                    pk(av[2*k],   av[2*k+1]))));
                    o15 = h[15];
                    m15 = av[15];
                    float d = z2;
                    #pragma unroll
                    for (int k = 0; k < 8; ++k) {
                        d = fmaf(ebv[2*k],   d, pb[k].x); h[2*k]   = d;
                        d = fmaf(ebv[2*k+1], d, pb[k].y); h[2*k+1] = d;
                    }

                    slot = (slot + 1 == RS) ? 0 : slot + 1;
                }
            } else {
                // ---- guarded head/tail (scalar, proven) ----
                #pragma unroll
                for (int q = 0; q < KP; ++q) {
                    const int s = t * KP + q;
                    if (s < STEPS) {
                        const float4* eb = (const float4*)(lane_base + slot * SLOTW);
                        const float4 A0 = eb[0], A1 = eb[1], A2 = eb[2], A3 = eb[3];
                        const float4 B0 = eb[4], B1 = eb[5], B2 = eb[6], B3 = eb[7];
                        float z0 = __shfl_up_sync(FULL, o15, 1);
                        float z1 = __shfl_up_sync(FULL, m15, 1);
                        float z2 = __shfl_up_sync(FULL, h[15], 1);
                        if (l == 0) {
                            z0 = (s == 0) ? 1.f : 0.f;   // virtual corner S[-1][-1]=1
                            z1 = 0.f; z2 = 0.f;
                        }
                        const bool act = (unsigned)(s - l) < (unsigned)NRP;

                        const float ea[16] = { A0.x, A0.y, A0.z, A0.w,
                                               A1.x, A1.y, A1.z, A1.w,
                                               A2.x, A2.y, A2.z, A2.w,
                                               A3.x, A3.y, A3.z, A3.w };
                        const float ebv[16] = { B0.x, B0.y, B0.z, B0.w,
                                                B1.x, B1.y, B1.z, B1.w,
                                                B2.x, B2.y, B2.z, B2.w,
                                                B3.x, B3.y, B3.z, B3.w };
                        float pa[16];
                        pa[0] = ea[0] * (z0 + h[0]);
                        #pragma unroll
                        for (int j = 1; j < 16; ++j) pa[j] = ea[j] * (h[j - 1] + h[j]);
                        float av[16];
                        float c = z1;
                        #pragma unroll
                        for (int j = 0; j < 16; ++j) { c = fmaf(ea[j], c, pa[j]); av[j] = c; }
                        float pb[16];
                        pb[0] = ebv[0] * (z1 + av[0]);
                        #pragma unroll
                        for (int j = 1; j < 16; ++j) pb[j] = ebv[j] * (av[j - 1] + av[j]);
                        const float o15n = h[15];
                        float d = z2;
                        #pragma unroll
                        for (int j = 0; j < 16; ++j) {
                            d = fmaf(ebv[j], d, pb[j]);
                            h[j] = act ? d : h[j];
                        }
                        o15 = act ? o15n   : o15;
                        m15 = act ? av[15] : m15;

                        slot = (slot + 1 == RS) ? 0 : slot + 1;
                    }
                }
            }
            if ((t % 5) == 4) rescale();   // every 30 steps: growth <= 9^30 < 2^127
        }
        // cell (511,511): lane 31, step 286, row b -> h[15]
        if (l == 31)
            out[b] = -(logf(h[15]) + (float)Es * 0.69314718055994531f);
    }
}

extern "C" void kernel_launch(void* const* d_in, const int* in_sizes, int n_in,
                              void* d_out, int out_size) {
    (void)in_sizes; (void)n_in; (void)out_size;
    const float* D = (const float*)d_in[0];
    float* o       = (float*)d_out;
    cudaFuncSetAttribute(softdtw_fwd, cudaFuncAttributeMaxDynamicSharedMemorySize, SMEM_BYTES);
    softdtw_fwd<<<BATCH, 128, SMEM_BYTES>>>(D, o);
}